// round 15
// baseline (speedup 1.0000x reference)
#include <cuda_runtime.h>
#include <cuda_bf16.h>
#include <cuda_fp16.h>
#include <math.h>
#include <stdint.h>

#define BATCH  2
#define CDIM   256
#define NHEADS 4
#define HDIM   64
#define NTOK   4096
#define BHDIM  (BATCH * NHEADS)
#define KT64   (NTOK / 64)

// ---- scratch (static device globals) ----
// Q/K/V fp16 (single): [bh][token][64d], 128B rows, 16B-chunk swizzle (row&7)
__device__ __half g_Qh[BHDIM * NTOK * HDIM];
__device__ __half g_Kh[BHDIM * NTOK * HDIM];
__device__ __half g_Vh[BHDIM * NTOK * HDIM];
// packed mask: 1 bit per element, [b][row][128 words of 32 cols]
__device__ uint32_t g_PM[BATCH * NTOK * (NTOK / 32)];
// X^T bf16 hi/lo: [b][n][256c], 512B rows, chunk low3 ^= row&7
__device__ __nv_bfloat16 g_Xh[BATCH * NTOK * CDIM];
__device__ __nv_bfloat16 g_Xl[BATCH * NTOK * CDIM];
// W (q,k,v stacked): [which*256+co][256c], 512B swizzled rows (bf16 hi/lo)
__device__ __nv_bfloat16 g_Wh[3 * CDIM * CDIM];
__device__ __nv_bfloat16 g_Wl[3 * CDIM * CDIM];
// Wo: [co][256c], fp16 hi/lo, 512B swizzled rows
__device__ __half g_Uh[CDIM * CDIM];
__device__ __half g_Ul[CDIM * CDIM];
// attention output fp16 single: [b][n][256c], 512B swizzled rows
__device__ __half g_Of[BATCH * NTOK * CDIM];

// ---- helpers ----
__device__ __forceinline__ uint32_t smem_u32(const void* p) {
    uint32_t a;
    asm("{ .reg .u64 t; cvta.to.shared.u64 t, %1; cvt.u32.u64 %0, t; }" : "=r"(a) : "l"(p));
    return a;
}
// bf16 mma (qkv projection)
__device__ __forceinline__ void mma16816(float* c, const uint32_t* a, uint32_t b0, uint32_t b1) {
    asm volatile("mma.sync.aligned.m16n8k16.row.col.f32.bf16.bf16.f32 "
        "{%0,%1,%2,%3}, {%4,%5,%6,%7}, {%8,%9}, {%0,%1,%2,%3};"
        : "+f"(c[0]), "+f"(c[1]), "+f"(c[2]), "+f"(c[3])
        : "r"(a[0]), "r"(a[1]), "r"(a[2]), "r"(a[3]), "r"(b0), "r"(b1));
}
// fp16 mma (attention, out-proj)
__device__ __forceinline__ void mma16816h(float* c, const uint32_t* a, uint32_t b0, uint32_t b1) {
    asm volatile("mma.sync.aligned.m16n8k16.row.col.f32.f16.f16.f32 "
        "{%0,%1,%2,%3}, {%4,%5,%6,%7}, {%8,%9}, {%0,%1,%2,%3};"
        : "+f"(c[0]), "+f"(c[1]), "+f"(c[2]), "+f"(c[3])
        : "r"(a[0]), "r"(a[1]), "r"(a[2]), "r"(a[3]), "r"(b0), "r"(b1));
}
__device__ __forceinline__ void ldsm4(uint32_t* r, uint32_t a) {
    asm volatile("ldmatrix.sync.aligned.m8n8.x4.shared.b16 {%0,%1,%2,%3}, [%4];"
        : "=r"(r[0]), "=r"(r[1]), "=r"(r[2]), "=r"(r[3]) : "r"(a));
}
__device__ __forceinline__ void ldsm4t(uint32_t* r, uint32_t a) {
    asm volatile("ldmatrix.sync.aligned.m8n8.x4.trans.shared.b16 {%0,%1,%2,%3}, [%4];"
        : "=r"(r[0]), "=r"(r[1]), "=r"(r[2]), "=r"(r[3]) : "r"(a));
}
__device__ __forceinline__ void cp16(uint32_t s, const void* g) {
    asm volatile("cp.async.cg.shared.global [%0], [%1], 16;" :: "r"(s), "l"(g) : "memory");
}
#define CP_COMMIT() asm volatile("cp.async.commit_group;" ::: "memory")
#define CP_WAIT(n)  asm volatile("cp.async.wait_group %0;" :: "n"(n) : "memory")

__device__ __forceinline__ float ex2f(float x) {
    float r; asm("ex2.approx.f32 %0, %1;" : "=f"(r) : "f"(x)); return r;
}
__device__ __forceinline__ uint32_t bf2_u32(__nv_bfloat162 v) {
    return *reinterpret_cast<uint32_t*>(&v);
}
__device__ __forceinline__ uint32_t h2_u32(__half2 v) {
    return *reinterpret_cast<uint32_t*>(&v);
}
// 128B-row swizzle (8 chunks)
__device__ __forceinline__ uint32_t swa(uint32_t base, int row, int chunk) {
    return base + (row << 7) + ((chunk ^ (row & 7)) << 4);
}
// 512B-row swizzle (32 chunks; only low 3 bits XOR'd)
__device__ __forceinline__ uint32_t swz512(uint32_t base, int row, int chunk) {
    return base + (row << 9) + (((chunk & 24) | ((chunk ^ row) & 7)) << 4);
}
__device__ __forceinline__ size_t swz512g(size_t row, int chunk) {
    return row * 512 + (size_t)(((chunk & 24) | ((chunk ^ (int)(row & 7)) & 7)) << 4);
}

// ============================================================================
// Prep 0: pack mask int32 -> bits (verified R14).
// ============================================================================
__global__ void __launch_bounds__(256) pack_mask_kernel(const int* __restrict__ mask)
{
    const int gw   = blockIdx.x * 8 + (threadIdx.x >> 5);
    const int lane = threadIdx.x & 31;
    int v = mask[(size_t)gw * 32 + lane];
    uint32_t bits = __ballot_sync(0xffffffffu, v != 0);
    if (lane == 0) g_PM[gw] = bits;
}

// ============================================================================
// Prep 1: split W. wq/wk/wv -> bf16 hi/lo (g_Wh/l); wo -> fp16 hi/lo (g_Uh/l).
// ============================================================================
__global__ void __launch_bounds__(256) split_w_kernel(
    const float* __restrict__ wq, const float* __restrict__ wk,
    const float* __restrict__ wv, const float* __restrict__ wo)
{
    const int r = blockIdx.x * 8 + (threadIdx.x >> 5);
    const int j = threadIdx.x & 31;
    const int m = r >> 8;
    const float* src = (m == 0) ? wq : (m == 1) ? wk : (m == 2) ? wv : wo;
    const float* s = src + (size_t)(r & 255) * 256 + j * 8;
    float4 v0 = *(const float4*)(s);
    float4 v1 = *(const float4*)(s + 4);
    float f[8] = {v0.x, v0.y, v0.z, v0.w, v1.x, v1.y, v1.z, v1.w};
    if (m < 3) {
        uint32_t hv[4], lv[4];
        #pragma unroll
        for (int e = 0; e < 4; e++) {
            __nv_bfloat162 hh = __floats2bfloat162_rn(f[2 * e], f[2 * e + 1]);
            __nv_bfloat162 ll = __floats2bfloat162_rn(f[2 * e] - __low2float(hh),
                                                      f[2 * e + 1] - __high2float(hh));
            hv[e] = bf2_u32(hh); lv[e] = bf2_u32(ll);
        }
        size_t off = swz512g((size_t)r, j);
        *(uint4*)((char*)g_Wh + off) = *(uint4*)hv;
        *(uint4*)((char*)g_Wl + off) = *(uint4*)lv;
    } else {
        uint32_t hv[4], lv[4];
        #pragma unroll
        for (int e = 0; e < 4; e++) {
            __half2 hh = __floats2half2_rn(f[2 * e], f[2 * e + 1]);
            __half2 ll = __floats2half2_rn(f[2 * e] - __low2float(hh),
                                           f[2 * e + 1] - __high2float(hh));
            hv[e] = h2_u32(hh); lv[e] = h2_u32(ll);
        }
        size_t off = swz512g((size_t)(r & 255), j);
        *(uint4*)((char*)g_Uh + off) = *(uint4*)hv;
        *(uint4*)((char*)g_Ul + off) = *(uint4*)lv;
    }
}

// ============================================================================
// Prep 2: split + transpose X -> g_Xh/l [b][n][256c] swizzled rows. (verified)
// ============================================================================
__global__ void __launch_bounds__(256) split_x_kernel(const float* __restrict__ x)
{
    __shared__ float Xs[64][65];
    const int n0 = blockIdx.x * 64;
    const int c0 = blockIdx.y * 64;
    const int b  = blockIdx.z;
    const int tid = threadIdx.x;

    #pragma unroll
    for (int it = 0; it < 4; it++) {
        int lin = tid + it * 256;
        int cc = lin >> 4, n4 = (lin & 15) * 4;
        float4 v = *(const float4*)&x[(size_t)(b * CDIM + c0 + cc) * NTOK + n0 + n4];
        Xs[cc][n4 + 0] = v.x; Xs[cc][n4 + 1] = v.y;
        Xs[cc][n4 + 2] = v.z; Xs[cc][n4 + 3] = v.w;
    }
    __syncthreads();

    const int nl = tid & 63;
    #pragma unroll
    for (int it = 0; it < 2; it++) {
        int cid = (tid >> 6) + it * 4;
        float f[8];
        #pragma unroll
        for (int e = 0; e < 8; e++) f[e] = Xs[cid * 8 + e][nl];
        uint32_t hv[4], lv[4];
        #pragma unroll
        for (int e = 0; e < 4; e++) {
            __nv_bfloat162 hh = __floats2bfloat162_rn(f[2 * e], f[2 * e + 1]);
            __nv_bfloat162 ll = __floats2bfloat162_rn(f[2 * e] - __low2float(hh),
                                                      f[2 * e + 1] - __high2float(hh));
            hv[e] = bf2_u32(hh); lv[e] = bf2_u32(ll);
        }
        size_t row = (size_t)(b * NTOK + n0 + nl);
        int chunk = blockIdx.y * 8 + cid;
        size_t off = swz512g(row, chunk);
        *(uint4*)((char*)g_Xh + off) = *(uint4*)hv;
        *(uint4*)((char*)g_Xl + off) = *(uint4*)lv;
    }
}

// ============================================================================
// Kernel: qkv via mma.sync, 2-stage c-half pipeline; epilogue -> fp16 single.
// ============================================================================
#define PSM_XH 0
#define PSM_XL 65536
#define PSM_WH 131072
#define PSM_WL 163840
#define PROJ_SMEM 196608

__global__ void __launch_bounds__(256, 1) qkv_mma_kernel(
    const float* __restrict__ bq, const float* __restrict__ bk, const float* __restrict__ bv)
{
    extern __shared__ char smem[];
    __shared__ float bias_s[64];
    const uint32_t sb = smem_u32(smem);
    const int tid = threadIdx.x;
    const int w = tid >> 5, L = tid & 31;
    const int gr = L >> 2, tc = L & 3;

    const int n0    = blockIdx.x * 128;
    const int which = blockIdx.y >> 2;
    const int h     = blockIdx.y & 3;
    const int b     = blockIdx.z;

    const char* xh = (const char*)g_Xh + (size_t)(b * NTOK + n0) * 512;
    const char* xl = (const char*)g_Xl + (size_t)(b * NTOK + n0) * 512;
    const char* wh = (const char*)g_Wh + (size_t)(which * 256 + h * 64) * 512;
    const char* wl = (const char*)g_Wl + (size_t)(which * 256 + h * 64) * 512;

    // stage A: bytes [0,256) of each row (chunks 0..15, used by kq 0..3)
    #pragma unroll
    for (int j = 0; j < 8; j++) {
        int idx = tid + j * 256;                 // 0..2047 (128 rows x 16 chunks)
        uint32_t off = (uint32_t)(((idx >> 4) << 9) + ((idx & 15) << 4));
        cp16(sb + PSM_XH + off, xh + off);
        cp16(sb + PSM_XL + off, xl + off);
    }
    #pragma unroll
    for (int j = 0; j < 2; j++) {
        int idx = tid + j * 256;                 // 0..511 (64 rows x 8... 16 half-chunks? 64x16=1024)
        // 64 rows x 16 chunks = 1024 entries -> 4 iters of 256; split 2+2 below
        uint32_t off = (uint32_t)(((idx >> 4) << 9) + ((idx & 15) << 4));
        cp16(sb + PSM_WH + off, wh + off);
        cp16(sb + PSM_WL + off, wl + off);
    }
    #pragma unroll
    for (int j = 2; j < 4; j++) {
        int idx = tid + j * 256;
        uint32_t off = (uint32_t)(((idx >> 4) << 9) + ((idx & 15) << 4));
        cp16(sb + PSM_WH + off, wh + off);
        cp16(sb + PSM_WL + off, wl + off);
    }
    CP_COMMIT();

    // stage B: bytes [256,512) of each row (chunks 16..31, used by kq 4..7)
    #pragma unroll
    for (int j = 0; j < 8; j++) {
        int idx = tid + j * 256;
        uint32_t off = (uint32_t)(((idx >> 4) << 9) + ((idx & 15) << 4) + 256);
        cp16(sb + PSM_XH + off, xh + off);
        cp16(sb + PSM_XL + off, xl + off);
    }
    #pragma unroll
    for (int j = 0; j < 4; j++) {
        int idx = tid + j * 256;
        uint32_t off = (uint32_t)(((idx >> 4) << 9) + ((idx & 15) << 4) + 256);
        cp16(sb + PSM_WH + off, wh + off);
        cp16(sb + PSM_WL + off, wl + off);
    }
    CP_COMMIT();

    if (tid < 64) {
        const float* bias = (which == 0) ? bq : (which == 1) ? bk : bv;
        bias_s[tid] = bias[h * 64 + tid];
    }

    float c[8][4];
    #pragma unroll
    for (int j = 0; j < 8; j++) { c[j][0] = c[j][1] = c[j][2] = c[j][3] = 0.0f; }

    const int arow = 16 * w + (L & 7) + (((L >> 3) & 1) << 3);

    CP_WAIT(1);
    __syncthreads();
    #pragma unroll
    for (int kq = 0; kq < 4; kq++) {
        uint32_t ah0[4], ah1[4], al0[4], al1[4];
        ldsm4(ah0, swz512(sb + PSM_XH, arow, 4 * kq + (L >> 4)));
        ldsm4(ah1, swz512(sb + PSM_XH, arow, 4 * kq + 2 + (L >> 4)));
        ldsm4(al0, swz512(sb + PSM_XL, arow, 4 * kq + (L >> 4)));
        ldsm4(al1, swz512(sb + PSM_XL, arow, 4 * kq + 2 + (L >> 4)));
        #pragma unroll
        for (int jt = 0; jt < 8; jt++) {
            uint32_t bh[4], bl[4];
            int brow = 8 * jt + (L & 7);
            ldsm4(bh, swz512(sb + PSM_WH, brow, 4 * kq + (L >> 3)));
            ldsm4(bl, swz512(sb + PSM_WL, brow, 4 * kq + (L >> 3)));
            mma16816(c[jt], ah0, bh[0], bh[1]);
            mma16816(c[jt], ah0, bl[0], bl[1]);
            mma16816(c[jt], al0, bh[0], bh[1]);
            mma16816(c[jt], ah1, bh[2], bh[3]);
            mma16816(c[jt], ah1, bl[2], bl[3]);
            mma16816(c[jt], al1, bh[2], bh[3]);
        }
    }
    CP_WAIT(0);
    __syncthreads();
    #pragma unroll
    for (int kq = 4; kq < 8; kq++) {
        uint32_t ah0[4], ah1[4], al0[4], al1[4];
        ldsm4(ah0, swz512(sb + PSM_XH, arow, 4 * kq + (L >> 4)));
        ldsm4(ah1, swz512(sb + PSM_XH, arow, 4 * kq + 2 + (L >> 4)));
        ldsm4(al0, swz512(sb + PSM_XL, arow, 4 * kq + (L >> 4)));
        ldsm4(al1, swz512(sb + PSM_XL, arow, 4 * kq + 2 + (L >> 4)));
        #pragma unroll
        for (int jt = 0; jt < 8; jt++) {
            uint32_t bh[4], bl[4];
            int brow = 8 * jt + (L & 7);
            ldsm4(bh, swz512(sb + PSM_WH, brow, 4 * kq + (L >> 3)));
            ldsm4(bl, swz512(sb + PSM_WL, brow, 4 * kq + (L >> 3)));
            mma16816(c[jt], ah0, bh[0], bh[1]);
            mma16816(c[jt], ah0, bl[0], bl[1]);
            mma16816(c[jt], al0, bh[0], bh[1]);
            mma16816(c[jt], ah1, bh[2], bh[3]);
            mma16816(c[jt], ah1, bl[2], bl[3]);
            mma16816(c[jt], al1, bh[2], bh[3]);
        }
    }

    __half* oh = (which == 0) ? g_Qh : (which == 1) ? g_Kh : g_Vh;
    const size_t bhbase = (size_t)(b * NHEADS + h) * NTOK;
    const int rA = n0 + 16 * w + gr;
    const int swl = rA & 7;
    #pragma unroll
    for (int jt = 0; jt < 8; jt++) {
        float b0 = bias_s[8 * jt + 2 * tc], b1 = bias_s[8 * jt + 2 * tc + 1];
        __half2 h01 = __floats2half2_rn(c[jt][0] + b0, c[jt][1] + b1);
        __half2 h23 = __floats2half2_rn(c[jt][2] + b0, c[jt][3] + b1);
        size_t off0 = (bhbase + rA) * 128 + (size_t)(((jt ^ swl) << 4) + 4 * tc);
        size_t off1 = (bhbase + rA + 8) * 128 + (size_t)(((jt ^ swl) << 4) + 4 * tc);
        *(uint32_t*)((char*)oh + off0) = h2_u32(h01);
        *(uint32_t*)((char*)oh + off1) = h2_u32(h23);
    }
}

// ============================================================================
// Kernel: flash attention, fp16 1-term, 8 warps x 16 q-rows (R12 shape),
// bit-packed mask (R14 logic), fp16 O epilogue. 48KB smem, 2 CTAs/SM.
// ============================================================================
#define SCLOG2 0.18033688f
#define SHLOG2 (-11.54156003f)
#define SM_Q     0
#define SM_BUF   16384
#define SM_BUFSZ 16384
#define ATTN_SMEM (16384 + 2 * SM_BUFSZ)

__device__ __forceinline__ void copy_tile64(uint32_t dst, const char* kh, const char* vh, int tid)
{
    #pragma unroll
    for (int j = 0; j < 2; j++) {
        uint32_t o = (uint32_t)(tid + j * 256) * 16;
        cp16(dst +        o, kh + o);
        cp16(dst + 8192 + o, vh + o);
    }
}

__global__ void __launch_bounds__(256, 2) attn_kernel()
{
    extern __shared__ char smem[];
    const uint32_t sb = smem_u32(smem);
    const int tid = threadIdx.x;
    const int w = tid >> 5, L = tid & 31;
    const int gr = L >> 2, tc = L & 3;

    const int q0 = blockIdx.x * 128;
    const int bh = blockIdx.y;
    const int b = bh >> 2, h = bh & 3;

    const size_t tb2 = (size_t)bh * NTOK * HDIM * 2;

    const char* qh_g = (const char*)g_Qh + tb2 + (size_t)q0 * 128;
    const char* kh_g = (const char*)g_Kh + tb2;
    const char* vh_g = (const char*)g_Vh + tb2;

    #pragma unroll
    for (int j = 0; j < 4; j++) {
        uint32_t o = (uint32_t)(tid + j * 256) * 16;
        cp16(sb + SM_Q + o, qh_g + o);
    }
    copy_tile64(sb + SM_BUF, kh_g, vh_g, tid);
    CP_COMMIT();
    copy_tile64(sb + SM_BUF + SM_BUFSZ, kh_g + 8192, vh_g + 8192, tid);
    CP_COMMIT();
    CP_WAIT(1);
    __syncthreads();

    uint32_t qh[4][4];
    #pragma unroll
    for (int ks = 0; ks < 4; ks++) {
        int row = (w << 4) + (L & 7) + (((L >> 3) & 1) << 3);
        int ch  = 2 * ks + (L >> 4);
        ldsm4(qh[ks], swa(sb + SM_Q, row, ch));
    }

    float o[8][4];
    #pragma unroll
    for (int i = 0; i < 8; i++) { o[i][0] = o[i][1] = o[i][2] = o[i][3] = 0.0f; }
    float l0 = 0.0f, l1 = 0.0f;

    const int r0 = q0 + w * 16 + gr;
    const uint32_t* pm0 = g_PM + ((size_t)b * NTOK + r0) * (NTOK / 32);
    const uint32_t* pm1 = pm0 + 8 * (NTOK / 32);

    for (int t = 0; t < KT64; t++) {
        const uint32_t kb = sb + SM_BUF + (t & 1) * SM_BUFSZ;

        // mask words for this tile (2 LDG.64; overlap S MMAs)
        uint2 mw0 = *(const uint2*)&pm0[t * 2];
        uint2 mw1 = *(const uint2*)&pm1[t * 2];

        // ---- S = Q K^T for this 64-key tile ----
        float s[8][4];
        #pragma unroll
        for (int n8 = 0; n8 < 8; n8++) { s[n8][0] = s[n8][1] = s[n8][2] = s[n8][3] = 0.0f; }

        #pragma unroll
        for (int n8 = 0; n8 < 8; n8++) {
            #pragma unroll
            for (int ksp = 0; ksp < 2; ksp++) {
                int row = 8 * n8 + (L & 7);
                int ch  = 4 * ksp + (L >> 3);
                uint32_t khf[4];
                ldsm4(khf, swa(kb, row, ch));
                mma16816h(s[n8], qh[2 * ksp],     khf[0], khf[1]);
                mma16816h(s[n8], qh[2 * ksp + 1], khf[2], khf[3]);
            }
        }

        // ---- fused softmax (bit mask) + PV per k16 group ----
        #pragma unroll
        for (int kp = 0; kp < 4; kp++) {
            uint32_t ah[4];
            #pragma unroll
            for (int e = 0; e < 2; e++) {
                int n8 = 2 * kp + e;
                int sh = (8 * n8 + 2 * tc) & 31;
                uint32_t wa = (n8 < 4) ? mw0.x : mw0.y;
                uint32_t wb = (n8 < 4) ? mw1.x : mw1.y;
                float f0 = (float)((wa >> sh) & 1u);
                float f1 = (float)((wa >> (sh + 1)) & 1u);
                float f2 = (float)((wb >> sh) & 1u);
                float f3 = (float)((wb >> (sh + 1)) & 1u);
                float p0 = f0 * ex2f(fmaf(s[n8][0], SCLOG2, SHLOG2));
                float p1 = f1 * ex2f(fmaf(s[n8][1], SCLOG2, SHLOG2));
                float p2 = f2 * ex2f(fmaf(s[n8][2], SCLOG2, SHLOG2));
                float p3 = f3 * ex2f(fmaf(s[n8][3], SCLOG2, SHLOG2));
                l0 += p0 + p1;
                l1 += p2 + p3;
                ah[2 * e]     = h2_u32(__floats2half2_rn(p0, p1));
                ah[2 * e + 1] = h2_u32(__floats2half2_rn(p2, p3));
            }
            #pragma unroll
            for (int dp = 0; dp < 4; dp++) {
                int row = (kp << 4) + (L & 7) + (((L >> 3) & 1) << 3);
                int ch  = 2 * dp + (L >> 4);
                uint32_t vhf[4];
                ldsm4t(vhf, swa(kb + 8192, row, ch));
                mma16816h(o[2 * dp],     ah, vhf[0], vhf[1]);
                mma16816h(o[2 * dp + 1], ah, vhf[2], vhf[3]);
            }
        }

        CP_WAIT(0);
        __syncthreads();
        if (t + 2 < KT64) {
            size_t off = (size_t)(t + 2) * 8192;
            copy_tile64(sb + SM_BUF + (t & 1) * SM_BUFSZ, kh_g + off, vh_g + off, tid);
            CP_COMMIT();
        }
    }

    l0 += __shfl_xor_sync(0xffffffffu, l0, 1);
    l0 += __shfl_xor_sync(0xffffffffu, l0, 2);
    l1 += __shfl_xor_sync(0xffffffffu, l1, 1);
    l1 += __shfl_xor_sync(0xffffffffu, l1, 2);
    float inv0 = 1.0f / l0, inv1 = 1.0f / l1;

    // epilogue: O fp16 single, [b][n][256c] 512B swizzled rows
    const int swl = r0 & 7;
    const size_t rowb0 = ((size_t)(b * NTOK + r0)) * 512;
    const size_t rowb1 = rowb0 + 8 * 512;
    #pragma unroll
    for (int dn = 0; dn < 8; dn++) {
        int chunk = h * 8 + dn;
        int chp = (chunk & 24) | ((chunk ^ swl) & 7);
        size_t off = (size_t)(chp * 16 + 4 * tc);
        *(uint32_t*)((char*)g_Of + rowb0 + off) =
            h2_u32(__floats2half2_rn(o[dn][0] * inv0, o[dn][1] * inv0));
        *(uint32_t*)((char*)g_Of + rowb1 + off) =
            h2_u32(__floats2half2_rn(o[dn][2] * inv1, o[dn][3] * inv1));
    }
}

// ============================================================================
// Kernel: out-proj fp16: A = wo hi/lo (2-term), B = O single. 4 MMAs/step.
// ============================================================================
#define OSM_O  0
#define OSM_UH 65536
#define OSM_UL 98304
#define OPROJ_SMEM 131072

__global__ void __launch_bounds__(256, 1) out_mma_kernel(
    const float* __restrict__ bo, float* __restrict__ y)
{
    extern __shared__ char smem[];
    __shared__ float bias_s[64];
    const uint32_t sb = smem_u32(smem);
    const int tid = threadIdx.x;
    const int w = tid >> 5, L = tid & 31;
    const int gr = L >> 2, tc = L & 3;
    const int mw = w & 3, nw = w >> 2;

    const int n0  = blockIdx.x * 128;
    const int co0 = blockIdx.y * 64;
    const int b   = blockIdx.z;

    const char* og = (const char*)g_Of + (size_t)(b * NTOK + n0) * 512;
    const char* uh = (const char*)g_Uh + (size_t)co0 * 512;
    const char* ul = (const char*)g_Ul + (size_t)co0 * 512;
    #pragma unroll
    for (int j = 0; j < 16; j++) {
        uint32_t o = (uint32_t)(tid + j * 256) * 16;
        cp16(sb + OSM_O + o, og + o);
    }
    #pragma unroll
    for (int j = 0; j < 8; j++) {
        uint32_t o = (uint32_t)(tid + j * 256) * 16;
        cp16(sb + OSM_UH + o, uh + o);
        cp16(sb + OSM_UL + o, ul + o);
    }
    if (tid < 64) bias_s[tid] = bo[co0 + tid];
    CP_COMMIT();
    CP_WAIT(0);
    __syncthreads();

    float c[8][4];
    #pragma unroll
    for (int j = 0; j < 8; j++) { c[j][0] = c[j][1] = c[j][2] = c[j][3] = 0.0f; }

    const int arow = 16 * mw + (L & 7) + (((L >> 3) & 1) << 3);
    #pragma unroll
    for (int kq = 0; kq < 8; kq++) {
        uint32_t ah0[4], ah1[4], al0[4], al1[4];
        ldsm4(ah0, swz512(sb + OSM_UH, arow, 4 * kq + (L >> 4)));
        ldsm4(ah1, swz512(sb + OSM_UH, arow, 4 * kq + 2 + (L >> 4)));
        ldsm4(al0, swz512(sb + OSM_UL, arow, 4 * kq + (L >> 4)));
        ldsm4(al1, swz512(sb + OSM_UL, arow, 4 * kq + 2 + (L >> 4)));
        #pragma unroll
        for (int jt = 0; jt < 8; jt++) {
            uint32_t bh[4];
            int brow = 64 * nw + 8 * jt + (L & 7);
            ldsm4(bh, swz512(sb + OSM_O, brow, 4 * kq + (L >> 3)));
            mma16816h(c[jt], ah0, bh[0], bh[1]);
            mma16816h(c[jt], al0, bh[0], bh[1]);
            mma16816h(c[jt], ah1, bh[2], bh[3]);
            mma16816h(c[jt], al1, bh[2], bh[3]);
        }
    }

    const int coA = co0 + 16 * mw + gr;
    const float bA = bias_s[16 * mw + gr];
    const float bB = bias_s[16 * mw + gr + 8];
    #pragma unroll
    for (int jt = 0; jt < 8; jt++) {
        int n = n0 + 64 * nw + 8 * jt + 2 * tc;
        float2 vA; vA.x = c[jt][0] + bA; vA.y = c[jt][1] + bA;
        float2 vB; vB.x = c[jt][2] + bB; vB.y = c[jt][3] + bB;
        *(float2*)&y[(size_t)(b * CDIM + coA) * NTOK + n] = vA;
        *(float2*)&y[(size_t)(b * CDIM + coA + 8) * NTOK + n] = vB;
    }
}

// ============================================================================
// Launch
// ============================================================================
extern "C" void kernel_launch(void* const* d_in, const int* in_sizes, int n_in,
                              void* d_out, int out_size)
{
    const float* x    = (const float*)d_in[0];
    const int*   mask = (const int*)d_in[1];
    const float* wq   = (const float*)d_in[2];
    const float* bq   = (const float*)d_in[3];
    const float* wk   = (const float*)d_in[4];
    const float* bk   = (const float*)d_in[5];
    const float* wv   = (const float*)d_in[6];
    const float* bv   = (const float*)d_in[7];
    const float* wo   = (const float*)d_in[8];
    const float* bo   = (const float*)d_in[9];
    float* y = (float*)d_out;

    cudaFuncSetAttribute(attn_kernel,
                         cudaFuncAttributeMaxDynamicSharedMemorySize, ATTN_SMEM);
    cudaFuncSetAttribute(qkv_mma_kernel,
                         cudaFuncAttributeMaxDynamicSharedMemorySize, PROJ_SMEM);
    cudaFuncSetAttribute(out_mma_kernel,
                         cudaFuncAttributeMaxDynamicSharedMemorySize, OPROJ_SMEM);

    pack_mask_kernel<<<BATCH * NTOK * (NTOK / 32) / 8, 256>>>(mask);
    split_w_kernel<<<128, 256>>>(wq, wk, wv, wo);
    split_x_kernel<<<dim3(64, 4, 2), 256>>>(x);
    qkv_mma_kernel<<<dim3(32, 12, 2), 256, PROJ_SMEM>>>(bq, bk, bv);
    attn_kernel<<<dim3(NTOK / 128, BHDIM), 256, ATTN_SMEM>>>();
    out_mma_kernel<<<dim3(32, 4, 2), 256, OPROJ_SMEM>>>(bo, y);
}

// round 16
// speedup vs baseline: 1.6098x; 1.6098x over previous
#include <cuda_runtime.h>
#include <cuda_bf16.h>
#include <cuda_fp16.h>
#include <math.h>
#include <stdint.h>

#define BATCH  2
#define CDIM   256
#define NHEADS 4
#define HDIM   64
#define NTOK   4096
#define BHDIM  (BATCH * NHEADS)
#define KT64   (NTOK / 64)

// ---- scratch (static device globals) ----
// Q/K/V fp16 (single): [bh][token][64d], 128B rows, 16B-chunk swizzle (row&7)
__device__ __half g_Qh[BHDIM * NTOK * HDIM];
__device__ __half g_Kh[BHDIM * NTOK * HDIM];
__device__ __half g_Vh[BHDIM * NTOK * HDIM];
// X^T bf16 hi/lo: [b][n][256c], 512B rows, chunk low3 ^= row&7
__device__ __nv_bfloat16 g_Xh[BATCH * NTOK * CDIM];
__device__ __nv_bfloat16 g_Xl[BATCH * NTOK * CDIM];
// W (q,k,v stacked): [which*256+co][256c], 512B swizzled rows (bf16 hi/lo)
__device__ __nv_bfloat16 g_Wh[3 * CDIM * CDIM];
__device__ __nv_bfloat16 g_Wl[3 * CDIM * CDIM];
// Wo: [co][256c], fp16 hi/lo, 512B swizzled rows
__device__ __half g_Uh[CDIM * CDIM];
__device__ __half g_Ul[CDIM * CDIM];
// attention output fp16 single: [b][n][256c], 512B swizzled rows
__device__ __half g_Of[BATCH * NTOK * CDIM];

// ---- helpers ----
__device__ __forceinline__ uint32_t smem_u32(const void* p) {
    uint32_t a;
    asm("{ .reg .u64 t; cvta.to.shared.u64 t, %1; cvt.u32.u64 %0, t; }" : "=r"(a) : "l"(p));
    return a;
}
// bf16 mma (qkv projection)
__device__ __forceinline__ void mma16816(float* c, const uint32_t* a, uint32_t b0, uint32_t b1) {
    asm volatile("mma.sync.aligned.m16n8k16.row.col.f32.bf16.bf16.f32 "
        "{%0,%1,%2,%3}, {%4,%5,%6,%7}, {%8,%9}, {%0,%1,%2,%3};"
        : "+f"(c[0]), "+f"(c[1]), "+f"(c[2]), "+f"(c[3])
        : "r"(a[0]), "r"(a[1]), "r"(a[2]), "r"(a[3]), "r"(b0), "r"(b1));
}
// fp16 mma (attention, out-proj)
__device__ __forceinline__ void mma16816h(float* c, const uint32_t* a, uint32_t b0, uint32_t b1) {
    asm volatile("mma.sync.aligned.m16n8k16.row.col.f32.f16.f16.f32 "
        "{%0,%1,%2,%3}, {%4,%5,%6,%7}, {%8,%9}, {%0,%1,%2,%3};"
        : "+f"(c[0]), "+f"(c[1]), "+f"(c[2]), "+f"(c[3])
        : "r"(a[0]), "r"(a[1]), "r"(a[2]), "r"(a[3]), "r"(b0), "r"(b1));
}
__device__ __forceinline__ void ldsm4(uint32_t* r, uint32_t a) {
    asm volatile("ldmatrix.sync.aligned.m8n8.x4.shared.b16 {%0,%1,%2,%3}, [%4];"
        : "=r"(r[0]), "=r"(r[1]), "=r"(r[2]), "=r"(r[3]) : "r"(a));
}
__device__ __forceinline__ void ldsm4t(uint32_t* r, uint32_t a) {
    asm volatile("ldmatrix.sync.aligned.m8n8.x4.trans.shared.b16 {%0,%1,%2,%3}, [%4];"
        : "=r"(r[0]), "=r"(r[1]), "=r"(r[2]), "=r"(r[3]) : "r"(a));
}
__device__ __forceinline__ void cp16(uint32_t s, const void* g) {
    asm volatile("cp.async.cg.shared.global [%0], [%1], 16;" :: "r"(s), "l"(g) : "memory");
}
#define CP_COMMIT() asm volatile("cp.async.commit_group;" ::: "memory")
#define CP_WAIT(n)  asm volatile("cp.async.wait_group %0;" :: "n"(n) : "memory")

__device__ __forceinline__ float ex2f(float x) {
    float r; asm("ex2.approx.f32 %0, %1;" : "=f"(r) : "f"(x)); return r;
}
__device__ __forceinline__ uint32_t bf2_u32(__nv_bfloat162 v) {
    return *reinterpret_cast<uint32_t*>(&v);
}
__device__ __forceinline__ uint32_t h2_u32(__half2 v) {
    return *reinterpret_cast<uint32_t*>(&v);
}
// 128B-row swizzle (8 chunks)
__device__ __forceinline__ uint32_t swa(uint32_t base, int row, int chunk) {
    return base + (row << 7) + ((chunk ^ (row & 7)) << 4);
}
// 512B-row swizzle (32 chunks; only low 3 bits XOR'd)
__device__ __forceinline__ uint32_t swz512(uint32_t base, int row, int chunk) {
    return base + (row << 9) + (((chunk & 24) | ((chunk ^ row) & 7)) << 4);
}
__device__ __forceinline__ size_t swz512g(size_t row, int chunk) {
    return row * 512 + (size_t)(((chunk & 24) | ((chunk ^ (int)(row & 7)) & 7)) << 4);
}

// ============================================================================
// Prep 1: split W. wq/wk/wv -> bf16 hi/lo (g_Wh/l); wo -> fp16 hi/lo (g_Uh/l).
// ============================================================================
__global__ void __launch_bounds__(256) split_w_kernel(
    const float* __restrict__ wq, const float* __restrict__ wk,
    const float* __restrict__ wv, const float* __restrict__ wo)
{
    const int r = blockIdx.x * 8 + (threadIdx.x >> 5);
    const int j = threadIdx.x & 31;
    const int m = r >> 8;
    const float* src = (m == 0) ? wq : (m == 1) ? wk : (m == 2) ? wv : wo;
    const float* s = src + (size_t)(r & 255) * 256 + j * 8;
    float4 v0 = *(const float4*)(s);
    float4 v1 = *(const float4*)(s + 4);
    float f[8] = {v0.x, v0.y, v0.z, v0.w, v1.x, v1.y, v1.z, v1.w};
    if (m < 3) {
        uint32_t hv[4], lv[4];
        #pragma unroll
        for (int e = 0; e < 4; e++) {
            __nv_bfloat162 hh = __floats2bfloat162_rn(f[2 * e], f[2 * e + 1]);
            __nv_bfloat162 ll = __floats2bfloat162_rn(f[2 * e] - __low2float(hh),
                                                      f[2 * e + 1] - __high2float(hh));
            hv[e] = bf2_u32(hh); lv[e] = bf2_u32(ll);
        }
        size_t off = swz512g((size_t)r, j);
        *(uint4*)((char*)g_Wh + off) = *(uint4*)hv;
        *(uint4*)((char*)g_Wl + off) = *(uint4*)lv;
    } else {
        uint32_t hv[4], lv[4];
        #pragma unroll
        for (int e = 0; e < 4; e++) {
            __half2 hh = __floats2half2_rn(f[2 * e], f[2 * e + 1]);
            __half2 ll = __floats2half2_rn(f[2 * e] - __low2float(hh),
                                           f[2 * e + 1] - __high2float(hh));
            hv[e] = h2_u32(hh); lv[e] = h2_u32(ll);
        }
        size_t off = swz512g((size_t)(r & 255), j);
        *(uint4*)((char*)g_Uh + off) = *(uint4*)hv;
        *(uint4*)((char*)g_Ul + off) = *(uint4*)lv;
    }
}

// ============================================================================
// Prep 2: split + transpose X -> g_Xh/l [b][n][256c] swizzled rows. (verified)
// ============================================================================
__global__ void __launch_bounds__(256) split_x_kernel(const float* __restrict__ x)
{
    __shared__ float Xs[64][65];
    const int n0 = blockIdx.x * 64;
    const int c0 = blockIdx.y * 64;
    const int b  = blockIdx.z;
    const int tid = threadIdx.x;

    #pragma unroll
    for (int it = 0; it < 4; it++) {
        int lin = tid + it * 256;
        int cc = lin >> 4, n4 = (lin & 15) * 4;
        float4 v = *(const float4*)&x[(size_t)(b * CDIM + c0 + cc) * NTOK + n0 + n4];
        Xs[cc][n4 + 0] = v.x; Xs[cc][n4 + 1] = v.y;
        Xs[cc][n4 + 2] = v.z; Xs[cc][n4 + 3] = v.w;
    }
    __syncthreads();

    const int nl = tid & 63;
    #pragma unroll
    for (int it = 0; it < 2; it++) {
        int cid = (tid >> 6) + it * 4;
        float f[8];
        #pragma unroll
        for (int e = 0; e < 8; e++) f[e] = Xs[cid * 8 + e][nl];
        uint32_t hv[4], lv[4];
        #pragma unroll
        for (int e = 0; e < 4; e++) {
            __nv_bfloat162 hh = __floats2bfloat162_rn(f[2 * e], f[2 * e + 1]);
            __nv_bfloat162 ll = __floats2bfloat162_rn(f[2 * e] - __low2float(hh),
                                                      f[2 * e + 1] - __high2float(hh));
            hv[e] = bf2_u32(hh); lv[e] = bf2_u32(ll);
        }
        size_t row = (size_t)(b * NTOK + n0 + nl);
        int chunk = blockIdx.y * 8 + cid;
        size_t off = swz512g(row, chunk);
        *(uint4*)((char*)g_Xh + off) = *(uint4*)hv;
        *(uint4*)((char*)g_Xl + off) = *(uint4*)lv;
    }
}

// ============================================================================
// Kernel: qkv via mma.sync (verified R8/R13 loader); epilogue -> fp16 single.
// ============================================================================
#define PSM_XH 0
#define PSM_XL 65536
#define PSM_WH 131072
#define PSM_WL 163840
#define PROJ_SMEM 196608

__global__ void __launch_bounds__(256, 1) qkv_mma_kernel(
    const float* __restrict__ bq, const float* __restrict__ bk, const float* __restrict__ bv)
{
    extern __shared__ char smem[];
    __shared__ float bias_s[64];
    const uint32_t sb = smem_u32(smem);
    const int tid = threadIdx.x;
    const int w = tid >> 5, L = tid & 31;
    const int gr = L >> 2, tc = L & 3;

    const int n0    = blockIdx.x * 128;
    const int which = blockIdx.y >> 2;
    const int h     = blockIdx.y & 3;
    const int b     = blockIdx.z;

    const char* xh = (const char*)g_Xh + (size_t)(b * NTOK + n0) * 512;
    const char* xl = (const char*)g_Xl + (size_t)(b * NTOK + n0) * 512;
    const char* wh = (const char*)g_Wh + (size_t)(which * 256 + h * 64) * 512;
    const char* wl = (const char*)g_Wl + (size_t)(which * 256 + h * 64) * 512;
    #pragma unroll
    for (int j = 0; j < 16; j++) {
        uint32_t o = (uint32_t)(tid + j * 256) * 16;
        cp16(sb + PSM_XH + o, xh + o);
        cp16(sb + PSM_XL + o, xl + o);
    }
    #pragma unroll
    for (int j = 0; j < 8; j++) {
        uint32_t o = (uint32_t)(tid + j * 256) * 16;
        cp16(sb + PSM_WH + o, wh + o);
        cp16(sb + PSM_WL + o, wl + o);
    }
    if (tid < 64) {
        const float* bias = (which == 0) ? bq : (which == 1) ? bk : bv;
        bias_s[tid] = bias[h * 64 + tid];
    }
    CP_COMMIT();
    CP_WAIT(0);
    __syncthreads();

    float c[8][4];
    #pragma unroll
    for (int j = 0; j < 8; j++) { c[j][0] = c[j][1] = c[j][2] = c[j][3] = 0.0f; }

    const int arow = 16 * w + (L & 7) + (((L >> 3) & 1) << 3);
    #pragma unroll
    for (int kq = 0; kq < 8; kq++) {
        uint32_t ah0[4], ah1[4], al0[4], al1[4];
        ldsm4(ah0, swz512(sb + PSM_XH, arow, 4 * kq + (L >> 4)));
        ldsm4(ah1, swz512(sb + PSM_XH, arow, 4 * kq + 2 + (L >> 4)));
        ldsm4(al0, swz512(sb + PSM_XL, arow, 4 * kq + (L >> 4)));
        ldsm4(al1, swz512(sb + PSM_XL, arow, 4 * kq + 2 + (L >> 4)));
        #pragma unroll
        for (int jt = 0; jt < 8; jt++) {
            uint32_t bh[4], bl[4];
            int brow = 8 * jt + (L & 7);
            ldsm4(bh, swz512(sb + PSM_WH, brow, 4 * kq + (L >> 3)));
            ldsm4(bl, swz512(sb + PSM_WL, brow, 4 * kq + (L >> 3)));
            mma16816(c[jt], ah0, bh[0], bh[1]);
            mma16816(c[jt], ah0, bl[0], bl[1]);
            mma16816(c[jt], al0, bh[0], bh[1]);
            mma16816(c[jt], ah1, bh[2], bh[3]);
            mma16816(c[jt], ah1, bl[2], bl[3]);
            mma16816(c[jt], al1, bh[2], bh[3]);
        }
    }

    __half* oh = (which == 0) ? g_Qh : (which == 1) ? g_Kh : g_Vh;
    const size_t bhbase = (size_t)(b * NHEADS + h) * NTOK;
    const int rA = n0 + 16 * w + gr;
    const int swl = rA & 7;
    #pragma unroll
    for (int jt = 0; jt < 8; jt++) {
        float b0 = bias_s[8 * jt + 2 * tc], b1 = bias_s[8 * jt + 2 * tc + 1];
        __half2 h01 = __floats2half2_rn(c[jt][0] + b0, c[jt][1] + b1);
        __half2 h23 = __floats2half2_rn(c[jt][2] + b0, c[jt][3] + b1);
        size_t off0 = (bhbase + rA) * 128 + (size_t)(((jt ^ swl) << 4) + 4 * tc);
        size_t off1 = (bhbase + rA + 8) * 128 + (size_t)(((jt ^ swl) << 4) + 4 * tc);
        *(uint32_t*)((char*)oh + off0) = h2_u32(h01);
        *(uint32_t*)((char*)oh + off1) = h2_u32(h23);
    }
}

// ============================================================================
// Kernel: flash attention (R13 verbatim: fp16 1-term, 4 warps x 32 q-rows,
// int32 mask) — only the epilogue changed: O -> fp16 single, 512B swizzled.
// ============================================================================
#define SCLOG2 0.18033688f
#define SHLOG2 (-11.54156003f)
#define SM_Q     0
#define SM_BUF   16384
#define SM_BUFSZ 16384
#define ATTN_SMEM (16384 + 2 * SM_BUFSZ)

__device__ __forceinline__ void copy_tile64(uint32_t dst, const char* kh, const char* vh, int tid)
{
    #pragma unroll
    for (int j = 0; j < 4; j++) {
        uint32_t o = (uint32_t)(tid + j * 128) * 16;
        cp16(dst +        o, kh + o);
        cp16(dst + 8192 + o, vh + o);
    }
}

__global__ void __launch_bounds__(128, 2) attn_kernel(const int* __restrict__ mask)
{
    extern __shared__ char smem[];
    const uint32_t sb = smem_u32(smem);
    const int tid = threadIdx.x;
    const int w = tid >> 5, L = tid & 31;
    const int gr = L >> 2, tc = L & 3;

    const int q0 = blockIdx.x * 128;
    const int bh = blockIdx.y;
    const int b = bh >> 2, h = bh & 3;

    const size_t tb2 = (size_t)bh * NTOK * HDIM * 2;   // byte base (fp16)

    const char* qh_g = (const char*)g_Qh + tb2 + (size_t)q0 * 128;
    const char* kh_g = (const char*)g_Kh + tb2;
    const char* vh_g = (const char*)g_Vh + tb2;

    #pragma unroll
    for (int j = 0; j < 8; j++) {
        uint32_t o = (uint32_t)(tid + j * 128) * 16;
        cp16(sb + SM_Q + o, qh_g + o);
    }
    copy_tile64(sb + SM_BUF, kh_g, vh_g, tid);
    CP_COMMIT();
    copy_tile64(sb + SM_BUF + SM_BUFSZ, kh_g + 8192, vh_g + 8192, tid);
    CP_COMMIT();
    CP_WAIT(1);
    __syncthreads();

    // Q fragments for two 16-row blocks: rows w*32+blk*16 .. +15
    uint32_t qh[2][4][4];
    #pragma unroll
    for (int blk = 0; blk < 2; blk++) {
        #pragma unroll
        for (int ks = 0; ks < 4; ks++) {
            int row = w * 32 + blk * 16 + (L & 7) + (((L >> 3) & 1) << 3);
            int ch  = 2 * ks + (L >> 4);
            ldsm4(qh[blk][ks], swa(sb + SM_Q, row, ch));
        }
    }

    float o[2][8][4];
    #pragma unroll
    for (int blk = 0; blk < 2; blk++)
        #pragma unroll
        for (int i = 0; i < 8; i++) {
            o[blk][i][0] = o[blk][i][1] = o[blk][i][2] = o[blk][i][3] = 0.0f;
        }
    float lsum[2][2] = {{0.0f, 0.0f}, {0.0f, 0.0f}};

    const size_t mb = (size_t)b * NTOK * NTOK;
    const int r00 = q0 + w * 32 + gr;            // blk0 row A (blk0 row B = +8)
    const int r10 = r00 + 16;                    // blk1 row A (row B = +24)
    const int2* mp[2][2];
    mp[0][0] = (const int2*)(mask + mb + (size_t)r00 * NTOK);
    mp[0][1] = (const int2*)(mask + mb + (size_t)(r00 + 8) * NTOK);
    mp[1][0] = (const int2*)(mask + mb + (size_t)r10 * NTOK);
    mp[1][1] = (const int2*)(mask + mb + (size_t)(r10 + 8) * NTOK);

    for (int t = 0; t < KT64; t++) {
        const uint32_t kb = sb + SM_BUF + (t & 1) * SM_BUFSZ;

        // ---- S = Q K^T : khf shared across both q blocks ----
        float s[2][8][4];
        #pragma unroll
        for (int blk = 0; blk < 2; blk++)
            #pragma unroll
            for (int n8 = 0; n8 < 8; n8++) {
                s[blk][n8][0] = s[blk][n8][1] = s[blk][n8][2] = s[blk][n8][3] = 0.0f;
            }

        #pragma unroll
        for (int n8 = 0; n8 < 8; n8++) {
            #pragma unroll
            for (int ksp = 0; ksp < 2; ksp++) {
                int row = 8 * n8 + (L & 7);
                int ch  = 4 * ksp + (L >> 3);
                uint32_t khf[4];
                ldsm4(khf, swa(kb, row, ch));
                #pragma unroll
                for (int blk = 0; blk < 2; blk++) {
                    mma16816h(s[blk][n8], qh[blk][2 * ksp],     khf[0], khf[1]);
                    mma16816h(s[blk][n8], qh[blk][2 * ksp + 1], khf[2], khf[3]);
                }
            }
        }

        // ---- fused softmax + PV; vhf shared across blocks ----
        #pragma unroll
        for (int kp = 0; kp < 4; kp++) {
            uint32_t ah[2][4];
            #pragma unroll
            for (int blk = 0; blk < 2; blk++) {
                #pragma unroll
                for (int e = 0; e < 2; e++) {
                    int n8 = 2 * kp + e;
                    int midx = t * 32 + 4 * n8 + tc;
                    int2 ma = mp[blk][0][midx];
                    int2 mbv = mp[blk][1][midx];
                    float p0 = ma.x ? ex2f(fmaf(s[blk][n8][0], SCLOG2, SHLOG2)) : 0.0f;
                    float p1 = ma.y ? ex2f(fmaf(s[blk][n8][1], SCLOG2, SHLOG2)) : 0.0f;
                    float p2 = mbv.x ? ex2f(fmaf(s[blk][n8][2], SCLOG2, SHLOG2)) : 0.0f;
                    float p3 = mbv.y ? ex2f(fmaf(s[blk][n8][3], SCLOG2, SHLOG2)) : 0.0f;
                    lsum[blk][0] += p0 + p1;
                    lsum[blk][1] += p2 + p3;
                    ah[blk][2 * e]     = h2_u32(__floats2half2_rn(p0, p1));
                    ah[blk][2 * e + 1] = h2_u32(__floats2half2_rn(p2, p3));
                }
            }
            #pragma unroll
            for (int dp = 0; dp < 4; dp++) {
                int row = (kp << 4) + (L & 7) + (((L >> 3) & 1) << 3);
                int ch  = 2 * dp + (L >> 4);
                uint32_t vhf[4];
                ldsm4t(vhf, swa(kb + 8192, row, ch));
                #pragma unroll
                for (int blk = 0; blk < 2; blk++) {
                    mma16816h(o[blk][2 * dp],     ah[blk], vhf[0], vhf[1]);
                    mma16816h(o[blk][2 * dp + 1], ah[blk], vhf[2], vhf[3]);
                }
            }
        }

        CP_WAIT(0);
        __syncthreads();
        if (t + 2 < KT64) {
            size_t off = (size_t)(t + 2) * 8192;
            copy_tile64(sb + SM_BUF + (t & 1) * SM_BUFSZ, kh_g + off, vh_g + off, tid);
            CP_COMMIT();
        }
    }

    // ---- reduce l over the 4 lanes sharing each row; write O fp16 swizzled --
    #pragma unroll
    for (int blk = 0; blk < 2; blk++) {
        float l0 = lsum[blk][0], l1 = lsum[blk][1];
        l0 += __shfl_xor_sync(0xffffffffu, l0, 1);
        l0 += __shfl_xor_sync(0xffffffffu, l0, 2);
        l1 += __shfl_xor_sync(0xffffffffu, l1, 1);
        l1 += __shfl_xor_sync(0xffffffffu, l1, 2);
        float inv0 = 1.0f / l0, inv1 = 1.0f / l1;

        const int r = q0 + w * 32 + blk * 16 + gr;
        const int swl = r & 7;                        // (r+8)&7 == r&7
        const size_t rowb0 = ((size_t)(b * NTOK + r)) * 512;
        const size_t rowb1 = rowb0 + 8 * 512;
        #pragma unroll
        for (int dn = 0; dn < 8; dn++) {
            int chunk = h * 8 + dn;
            int chp = (chunk & 24) | ((chunk ^ swl) & 7);
            size_t off = (size_t)(chp * 16 + 4 * tc);
            *(uint32_t*)((char*)g_Of + rowb0 + off) =
                h2_u32(__floats2half2_rn(o[blk][dn][0] * inv0, o[blk][dn][1] * inv0));
            *(uint32_t*)((char*)g_Of + rowb1 + off) =
                h2_u32(__floats2half2_rn(o[blk][dn][2] * inv1, o[blk][dn][3] * inv1));
        }
    }
}

// ============================================================================
// Kernel: out-proj fp16: A = wo hi/lo (2-term), B = O single. 4 MMAs/step.
// ============================================================================
#define OSM_O  0
#define OSM_UH 65536
#define OSM_UL 98304
#define OPROJ_SMEM 131072

__global__ void __launch_bounds__(256, 1) out_mma_kernel(
    const float* __restrict__ bo, float* __restrict__ y)
{
    extern __shared__ char smem[];
    __shared__ float bias_s[64];
    const uint32_t sb = smem_u32(smem);
    const int tid = threadIdx.x;
    const int w = tid >> 5, L = tid & 31;
    const int gr = L >> 2, tc = L & 3;
    const int mw = w & 3, nw = w >> 2;

    const int n0  = blockIdx.x * 128;
    const int co0 = blockIdx.y * 64;
    const int b   = blockIdx.z;

    const char* og = (const char*)g_Of + (size_t)(b * NTOK + n0) * 512;
    const char* uh = (const char*)g_Uh + (size_t)co0 * 512;
    const char* ul = (const char*)g_Ul + (size_t)co0 * 512;
    #pragma unroll
    for (int j = 0; j < 16; j++) {
        uint32_t o = (uint32_t)(tid + j * 256) * 16;
        cp16(sb + OSM_O + o, og + o);
    }
    #pragma unroll
    for (int j = 0; j < 8; j++) {
        uint32_t o = (uint32_t)(tid + j * 256) * 16;
        cp16(sb + OSM_UH + o, uh + o);
        cp16(sb + OSM_UL + o, ul + o);
    }
    if (tid < 64) bias_s[tid] = bo[co0 + tid];
    CP_COMMIT();
    CP_WAIT(0);
    __syncthreads();

    float c[8][4];
    #pragma unroll
    for (int j = 0; j < 8; j++) { c[j][0] = c[j][1] = c[j][2] = c[j][3] = 0.0f; }

    const int arow = 16 * mw + (L & 7) + (((L >> 3) & 1) << 3);
    #pragma unroll
    for (int kq = 0; kq < 8; kq++) {
        uint32_t ah0[4], ah1[4], al0[4], al1[4];
        ldsm4(ah0, swz512(sb + OSM_UH, arow, 4 * kq + (L >> 4)));
        ldsm4(ah1, swz512(sb + OSM_UH, arow, 4 * kq + 2 + (L >> 4)));
        ldsm4(al0, swz512(sb + OSM_UL, arow, 4 * kq + (L >> 4)));
        ldsm4(al1, swz512(sb + OSM_UL, arow, 4 * kq + 2 + (L >> 4)));
        #pragma unroll
        for (int jt = 0; jt < 8; jt++) {
            uint32_t bh[4];
            int brow = 64 * nw + 8 * jt + (L & 7);
            ldsm4(bh, swz512(sb + OSM_O, brow, 4 * kq + (L >> 3)));
            mma16816h(c[jt], ah0, bh[0], bh[1]);
            mma16816h(c[jt], al0, bh[0], bh[1]);
            mma16816h(c[jt], ah1, bh[2], bh[3]);
            mma16816h(c[jt], al1, bh[2], bh[3]);
        }
    }

    const int coA = co0 + 16 * mw + gr;
    const float bA = bias_s[16 * mw + gr];
    const float bB = bias_s[16 * mw + gr + 8];
    #pragma unroll
    for (int jt = 0; jt < 8; jt++) {
        int n = n0 + 64 * nw + 8 * jt + 2 * tc;
        float2 vA; vA.x = c[jt][0] + bA; vA.y = c[jt][1] + bA;
        float2 vB; vB.x = c[jt][2] + bB; vB.y = c[jt][3] + bB;
        *(float2*)&y[(size_t)(b * CDIM + coA) * NTOK + n] = vA;
        *(float2*)&y[(size_t)(b * CDIM + coA + 8) * NTOK + n] = vB;
    }
}

// ============================================================================
// Launch
// ============================================================================
extern "C" void kernel_launch(void* const* d_in, const int* in_sizes, int n_in,
                              void* d_out, int out_size)
{
    const float* x    = (const float*)d_in[0];
    const int*   mask = (const int*)d_in[1];
    const float* wq   = (const float*)d_in[2];
    const float* bq   = (const float*)d_in[3];
    const float* wk   = (const float*)d_in[4];
    const float* bk   = (const float*)d_in[5];
    const float* wv   = (const float*)d_in[6];
    const float* bv   = (const float*)d_in[7];
    const float* wo   = (const float*)d_in[8];
    const float* bo   = (const float*)d_in[9];
    float* y = (float*)d_out;

    cudaFuncSetAttribute(attn_kernel,
                         cudaFuncAttributeMaxDynamicSharedMemorySize, ATTN_SMEM);
    cudaFuncSetAttribute(qkv_mma_kernel,
                         cudaFuncAttributeMaxDynamicSharedMemorySize, PROJ_SMEM);
    cudaFuncSetAttribute(out_mma_kernel,
                         cudaFuncAttributeMaxDynamicSharedMemorySize, OPROJ_SMEM);

    split_w_kernel<<<128, 256>>>(wq, wk, wv, wo);
    split_x_kernel<<<dim3(64, 4, 2), 256>>>(x);
    qkv_mma_kernel<<<dim3(32, 12, 2), 256, PROJ_SMEM>>>(bq, bk, bv);
    attn_kernel<<<dim3(NTOK / 128, BHDIM), 128, ATTN_SMEM>>>(mask);
    out_mma_kernel<<<dim3(32, 4, 2), 256, OPROJ_SMEM>>>(bo, y);
}

// round 17
// speedup vs baseline: 1.6843x; 1.0463x over previous
#include <cuda_runtime.h>
#include <cuda_bf16.h>
#include <cuda_fp16.h>
#include <math.h>
#include <stdint.h>

#define BATCH  2
#define CDIM   256
#define NHEADS 4
#define HDIM   64
#define NTOK   4096
#define BHDIM  (BATCH * NHEADS)
#define KT64   (NTOK / 64)

// ---- scratch (static device globals) ----
// Q/K/V fp16 (single): [bh][token][64d], 128B rows, 16B-chunk swizzle (row&7)
__device__ __half g_Qh[BHDIM * NTOK * HDIM];
__device__ __half g_Kh[BHDIM * NTOK * HDIM];
__device__ __half g_Vh[BHDIM * NTOK * HDIM];
// X^T bf16 hi/lo: [b][n][256c], 512B rows, chunk low3 ^= row&7
__device__ __nv_bfloat16 g_Xh[BATCH * NTOK * CDIM];
__device__ __nv_bfloat16 g_Xl[BATCH * NTOK * CDIM];
// W (q,k,v stacked): [which*256+co][256c], 512B swizzled rows (bf16 hi/lo)
__device__ __nv_bfloat16 g_Wh[3 * CDIM * CDIM];
__device__ __nv_bfloat16 g_Wl[3 * CDIM * CDIM];
// Wo: [co][256c], fp16 hi/lo, 512B swizzled rows
__device__ __half g_Uh[CDIM * CDIM];
__device__ __half g_Ul[CDIM * CDIM];
// attention output fp16 single: [b][n][256c], 512B swizzled rows
__device__ __half g_Of[BATCH * NTOK * CDIM];

// ---- helpers ----
__device__ __forceinline__ uint32_t smem_u32(const void* p) {
    uint32_t a;
    asm("{ .reg .u64 t; cvta.to.shared.u64 t, %1; cvt.u32.u64 %0, t; }" : "=r"(a) : "l"(p));
    return a;
}
// bf16 mma (qkv projection)
__device__ __forceinline__ void mma16816(float* c, const uint32_t* a, uint32_t b0, uint32_t b1) {
    asm volatile("mma.sync.aligned.m16n8k16.row.col.f32.bf16.bf16.f32 "
        "{%0,%1,%2,%3}, {%4,%5,%6,%7}, {%8,%9}, {%0,%1,%2,%3};"
        : "+f"(c[0]), "+f"(c[1]), "+f"(c[2]), "+f"(c[3])
        : "r"(a[0]), "r"(a[1]), "r"(a[2]), "r"(a[3]), "r"(b0), "r"(b1));
}
// fp16 mma (attention, out-proj)
__device__ __forceinline__ void mma16816h(float* c, const uint32_t* a, uint32_t b0, uint32_t b1) {
    asm volatile("mma.sync.aligned.m16n8k16.row.col.f32.f16.f16.f32 "
        "{%0,%1,%2,%3}, {%4,%5,%6,%7}, {%8,%9}, {%0,%1,%2,%3};"
        : "+f"(c[0]), "+f"(c[1]), "+f"(c[2]), "+f"(c[3])
        : "r"(a[0]), "r"(a[1]), "r"(a[2]), "r"(a[3]), "r"(b0), "r"(b1));
}
__device__ __forceinline__ void ldsm4(uint32_t* r, uint32_t a) {
    asm volatile("ldmatrix.sync.aligned.m8n8.x4.shared.b16 {%0,%1,%2,%3}, [%4];"
        : "=r"(r[0]), "=r"(r[1]), "=r"(r[2]), "=r"(r[3]) : "r"(a));
}
__device__ __forceinline__ void ldsm4t(uint32_t* r, uint32_t a) {
    asm volatile("ldmatrix.sync.aligned.m8n8.x4.trans.shared.b16 {%0,%1,%2,%3}, [%4];"
        : "=r"(r[0]), "=r"(r[1]), "=r"(r[2]), "=r"(r[3]) : "r"(a));
}
__device__ __forceinline__ void cp16(uint32_t s, const void* g) {
    asm volatile("cp.async.cg.shared.global [%0], [%1], 16;" :: "r"(s), "l"(g) : "memory");
}
#define CP_COMMIT() asm volatile("cp.async.commit_group;" ::: "memory")
#define CP_WAIT(n)  asm volatile("cp.async.wait_group %0;" :: "n"(n) : "memory")

__device__ __forceinline__ float ex2f(float x) {
    float r; asm("ex2.approx.f32 %0, %1;" : "=f"(r) : "f"(x)); return r;
}
__device__ __forceinline__ uint32_t bf2_u32(__nv_bfloat162 v) {
    return *reinterpret_cast<uint32_t*>(&v);
}
__device__ __forceinline__ uint32_t h2_u32(__half2 v) {
    return *reinterpret_cast<uint32_t*>(&v);
}
// 128B-row swizzle (8 chunks)
__device__ __forceinline__ uint32_t swa(uint32_t base, int row, int chunk) {
    return base + (row << 7) + ((chunk ^ (row & 7)) << 4);
}
// 512B-row swizzle (32 chunks; only low 3 bits XOR'd)
__device__ __forceinline__ uint32_t swz512(uint32_t base, int row, int chunk) {
    return base + (row << 9) + (((chunk & 24) | ((chunk ^ row) & 7)) << 4);
}
__device__ __forceinline__ size_t swz512g(size_t row, int chunk) {
    return row * 512 + (size_t)(((chunk & 24) | ((chunk ^ (int)(row & 7)) & 7)) << 4);
}

// ============================================================================
// Prep 1: split W. wq/wk/wv -> bf16 hi/lo (g_Wh/l); wo -> fp16 hi/lo (g_Uh/l).
// ============================================================================
__global__ void __launch_bounds__(256) split_w_kernel(
    const float* __restrict__ wq, const float* __restrict__ wk,
    const float* __restrict__ wv, const float* __restrict__ wo)
{
    const int r = blockIdx.x * 8 + (threadIdx.x >> 5);
    const int j = threadIdx.x & 31;
    const int m = r >> 8;
    const float* src = (m == 0) ? wq : (m == 1) ? wk : (m == 2) ? wv : wo;
    const float* s = src + (size_t)(r & 255) * 256 + j * 8;
    float4 v0 = *(const float4*)(s);
    float4 v1 = *(const float4*)(s + 4);
    float f[8] = {v0.x, v0.y, v0.z, v0.w, v1.x, v1.y, v1.z, v1.w};
    if (m < 3) {
        uint32_t hv[4], lv[4];
        #pragma unroll
        for (int e = 0; e < 4; e++) {
            __nv_bfloat162 hh = __floats2bfloat162_rn(f[2 * e], f[2 * e + 1]);
            __nv_bfloat162 ll = __floats2bfloat162_rn(f[2 * e] - __low2float(hh),
                                                      f[2 * e + 1] - __high2float(hh));
            hv[e] = bf2_u32(hh); lv[e] = bf2_u32(ll);
        }
        size_t off = swz512g((size_t)r, j);
        *(uint4*)((char*)g_Wh + off) = *(uint4*)hv;
        *(uint4*)((char*)g_Wl + off) = *(uint4*)lv;
    } else {
        uint32_t hv[4], lv[4];
        #pragma unroll
        for (int e = 0; e < 4; e++) {
            __half2 hh = __floats2half2_rn(f[2 * e], f[2 * e + 1]);
            __half2 ll = __floats2half2_rn(f[2 * e] - __low2float(hh),
                                           f[2 * e + 1] - __high2float(hh));
            hv[e] = h2_u32(hh); lv[e] = h2_u32(ll);
        }
        size_t off = swz512g((size_t)(r & 255), j);
        *(uint4*)((char*)g_Uh + off) = *(uint4*)hv;
        *(uint4*)((char*)g_Ul + off) = *(uint4*)lv;
    }
}

// ============================================================================
// Prep 2: split + transpose X -> g_Xh/l [b][n][256c] swizzled rows. (verified)
// ============================================================================
__global__ void __launch_bounds__(256) split_x_kernel(const float* __restrict__ x)
{
    __shared__ float Xs[64][65];
    const int n0 = blockIdx.x * 64;
    const int c0 = blockIdx.y * 64;
    const int b  = blockIdx.z;
    const int tid = threadIdx.x;

    #pragma unroll
    for (int it = 0; it < 4; it++) {
        int lin = tid + it * 256;
        int cc = lin >> 4, n4 = (lin & 15) * 4;
        float4 v = *(const float4*)&x[(size_t)(b * CDIM + c0 + cc) * NTOK + n0 + n4];
        Xs[cc][n4 + 0] = v.x; Xs[cc][n4 + 1] = v.y;
        Xs[cc][n4 + 2] = v.z; Xs[cc][n4 + 3] = v.w;
    }
    __syncthreads();

    const int nl = tid & 63;
    #pragma unroll
    for (int it = 0; it < 2; it++) {
        int cid = (tid >> 6) + it * 4;
        float f[8];
        #pragma unroll
        for (int e = 0; e < 8; e++) f[e] = Xs[cid * 8 + e][nl];
        uint32_t hv[4], lv[4];
        #pragma unroll
        for (int e = 0; e < 4; e++) {
            __nv_bfloat162 hh = __floats2bfloat162_rn(f[2 * e], f[2 * e + 1]);
            __nv_bfloat162 ll = __floats2bfloat162_rn(f[2 * e] - __low2float(hh),
                                                      f[2 * e + 1] - __high2float(hh));
            hv[e] = bf2_u32(hh); lv[e] = bf2_u32(ll);
        }
        size_t row = (size_t)(b * NTOK + n0 + nl);
        int chunk = blockIdx.y * 8 + cid;
        size_t off = swz512g(row, chunk);
        *(uint4*)((char*)g_Xh + off) = *(uint4*)hv;
        *(uint4*)((char*)g_Xl + off) = *(uint4*)lv;
    }
}

// ============================================================================
// Kernel: qkv via mma.sync (verified loader); epilogue -> fp16 single.
// ============================================================================
#define PSM_XH 0
#define PSM_XL 65536
#define PSM_WH 131072
#define PSM_WL 163840
#define PROJ_SMEM 196608

__global__ void __launch_bounds__(256, 1) qkv_mma_kernel(
    const float* __restrict__ bq, const float* __restrict__ bk, const float* __restrict__ bv)
{
    extern __shared__ char smem[];
    __shared__ float bias_s[64];
    const uint32_t sb = smem_u32(smem);
    const int tid = threadIdx.x;
    const int w = tid >> 5, L = tid & 31;
    const int gr = L >> 2, tc = L & 3;

    const int n0    = blockIdx.x * 128;
    const int which = blockIdx.y >> 2;
    const int h     = blockIdx.y & 3;
    const int b     = blockIdx.z;

    const char* xh = (const char*)g_Xh + (size_t)(b * NTOK + n0) * 512;
    const char* xl = (const char*)g_Xl + (size_t)(b * NTOK + n0) * 512;
    const char* wh = (const char*)g_Wh + (size_t)(which * 256 + h * 64) * 512;
    const char* wl = (const char*)g_Wl + (size_t)(which * 256 + h * 64) * 512;
    #pragma unroll
    for (int j = 0; j < 16; j++) {
        uint32_t o = (uint32_t)(tid + j * 256) * 16;
        cp16(sb + PSM_XH + o, xh + o);
        cp16(sb + PSM_XL + o, xl + o);
    }
    #pragma unroll
    for (int j = 0; j < 8; j++) {
        uint32_t o = (uint32_t)(tid + j * 256) * 16;
        cp16(sb + PSM_WH + o, wh + o);
        cp16(sb + PSM_WL + o, wl + o);
    }
    if (tid < 64) {
        const float* bias = (which == 0) ? bq : (which == 1) ? bk : bv;
        bias_s[tid] = bias[h * 64 + tid];
    }
    CP_COMMIT();
    CP_WAIT(0);
    __syncthreads();

    float c[8][4];
    #pragma unroll
    for (int j = 0; j < 8; j++) { c[j][0] = c[j][1] = c[j][2] = c[j][3] = 0.0f; }

    const int arow = 16 * w + (L & 7) + (((L >> 3) & 1) << 3);
    #pragma unroll
    for (int kq = 0; kq < 8; kq++) {
        uint32_t ah0[4], ah1[4], al0[4], al1[4];
        ldsm4(ah0, swz512(sb + PSM_XH, arow, 4 * kq + (L >> 4)));
        ldsm4(ah1, swz512(sb + PSM_XH, arow, 4 * kq + 2 + (L >> 4)));
        ldsm4(al0, swz512(sb + PSM_XL, arow, 4 * kq + (L >> 4)));
        ldsm4(al1, swz512(sb + PSM_XL, arow, 4 * kq + 2 + (L >> 4)));
        #pragma unroll
        for (int jt = 0; jt < 8; jt++) {
            uint32_t bh[4], bl[4];
            int brow = 8 * jt + (L & 7);
            ldsm4(bh, swz512(sb + PSM_WH, brow, 4 * kq + (L >> 3)));
            ldsm4(bl, swz512(sb + PSM_WL, brow, 4 * kq + (L >> 3)));
            mma16816(c[jt], ah0, bh[0], bh[1]);
            mma16816(c[jt], ah0, bl[0], bl[1]);
            mma16816(c[jt], al0, bh[0], bh[1]);
            mma16816(c[jt], ah1, bh[2], bh[3]);
            mma16816(c[jt], ah1, bl[2], bl[3]);
            mma16816(c[jt], al1, bh[2], bh[3]);
        }
    }

    __half* oh = (which == 0) ? g_Qh : (which == 1) ? g_Kh : g_Vh;
    const size_t bhbase = (size_t)(b * NHEADS + h) * NTOK;
    const int rA = n0 + 16 * w + gr;
    const int swl = rA & 7;
    #pragma unroll
    for (int jt = 0; jt < 8; jt++) {
        float b0 = bias_s[8 * jt + 2 * tc], b1 = bias_s[8 * jt + 2 * tc + 1];
        __half2 h01 = __floats2half2_rn(c[jt][0] + b0, c[jt][1] + b1);
        __half2 h23 = __floats2half2_rn(c[jt][2] + b0, c[jt][3] + b1);
        size_t off0 = (bhbase + rA) * 128 + (size_t)(((jt ^ swl) << 4) + 4 * tc);
        size_t off1 = (bhbase + rA + 8) * 128 + (size_t)(((jt ^ swl) << 4) + 4 * tc);
        *(uint32_t*)((char*)oh + off0) = h2_u32(h01);
        *(uint32_t*)((char*)oh + off1) = h2_u32(h23);
    }
}

// ============================================================================
// Kernel: flash attention (R13 mainloop verbatim). Epilogue: stage O fp16 in
// smem (144B row stride), then coalesced 16B global stores to g_Of.
// ============================================================================
#define SCLOG2 0.18033688f
#define SHLOG2 (-11.54156003f)
#define SM_Q     0
#define SM_BUF   16384
#define SM_BUFSZ 16384
#define ATTN_SMEM (16384 + 2 * SM_BUFSZ)

__device__ __forceinline__ void copy_tile64(uint32_t dst, const char* kh, const char* vh, int tid)
{
    #pragma unroll
    for (int j = 0; j < 4; j++) {
        uint32_t o = (uint32_t)(tid + j * 128) * 16;
        cp16(dst +        o, kh + o);
        cp16(dst + 8192 + o, vh + o);
    }
}

__global__ void __launch_bounds__(128, 2) attn_kernel(const int* __restrict__ mask)
{
    extern __shared__ char smem[];
    const uint32_t sb = smem_u32(smem);
    const int tid = threadIdx.x;
    const int w = tid >> 5, L = tid & 31;
    const int gr = L >> 2, tc = L & 3;

    const int q0 = blockIdx.x * 128;
    const int bh = blockIdx.y;
    const int b = bh >> 2, h = bh & 3;

    const size_t tb2 = (size_t)bh * NTOK * HDIM * 2;   // byte base (fp16)

    const char* qh_g = (const char*)g_Qh + tb2 + (size_t)q0 * 128;
    const char* kh_g = (const char*)g_Kh + tb2;
    const char* vh_g = (const char*)g_Vh + tb2;

    #pragma unroll
    for (int j = 0; j < 8; j++) {
        uint32_t o = (uint32_t)(tid + j * 128) * 16;
        cp16(sb + SM_Q + o, qh_g + o);
    }
    copy_tile64(sb + SM_BUF, kh_g, vh_g, tid);
    CP_COMMIT();
    copy_tile64(sb + SM_BUF + SM_BUFSZ, kh_g + 8192, vh_g + 8192, tid);
    CP_COMMIT();
    CP_WAIT(1);
    __syncthreads();

    // Q fragments for two 16-row blocks: rows w*32+blk*16 .. +15
    uint32_t qh[2][4][4];
    #pragma unroll
    for (int blk = 0; blk < 2; blk++) {
        #pragma unroll
        for (int ks = 0; ks < 4; ks++) {
            int row = w * 32 + blk * 16 + (L & 7) + (((L >> 3) & 1) << 3);
            int ch  = 2 * ks + (L >> 4);
            ldsm4(qh[blk][ks], swa(sb + SM_Q, row, ch));
        }
    }

    float o[2][8][4];
    #pragma unroll
    for (int blk = 0; blk < 2; blk++)
        #pragma unroll
        for (int i = 0; i < 8; i++) {
            o[blk][i][0] = o[blk][i][1] = o[blk][i][2] = o[blk][i][3] = 0.0f;
        }
    float lsum[2][2] = {{0.0f, 0.0f}, {0.0f, 0.0f}};

    const size_t mb = (size_t)b * NTOK * NTOK;
    const int r00 = q0 + w * 32 + gr;
    const int r10 = r00 + 16;
    const int2* mp[2][2];
    mp[0][0] = (const int2*)(mask + mb + (size_t)r00 * NTOK);
    mp[0][1] = (const int2*)(mask + mb + (size_t)(r00 + 8) * NTOK);
    mp[1][0] = (const int2*)(mask + mb + (size_t)r10 * NTOK);
    mp[1][1] = (const int2*)(mask + mb + (size_t)(r10 + 8) * NTOK);

    for (int t = 0; t < KT64; t++) {
        const uint32_t kb = sb + SM_BUF + (t & 1) * SM_BUFSZ;

        // ---- S = Q K^T : khf shared across both q blocks ----
        float s[2][8][4];
        #pragma unroll
        for (int blk = 0; blk < 2; blk++)
            #pragma unroll
            for (int n8 = 0; n8 < 8; n8++) {
                s[blk][n8][0] = s[blk][n8][1] = s[blk][n8][2] = s[blk][n8][3] = 0.0f;
            }

        #pragma unroll
        for (int n8 = 0; n8 < 8; n8++) {
            #pragma unroll
            for (int ksp = 0; ksp < 2; ksp++) {
                int row = 8 * n8 + (L & 7);
                int ch  = 4 * ksp + (L >> 3);
                uint32_t khf[4];
                ldsm4(khf, swa(kb, row, ch));
                #pragma unroll
                for (int blk = 0; blk < 2; blk++) {
                    mma16816h(s[blk][n8], qh[blk][2 * ksp],     khf[0], khf[1]);
                    mma16816h(s[blk][n8], qh[blk][2 * ksp + 1], khf[2], khf[3]);
                }
            }
        }

        // ---- fused softmax + PV; vhf shared across blocks ----
        #pragma unroll
        for (int kp = 0; kp < 4; kp++) {
            uint32_t ah[2][4];
            #pragma unroll
            for (int blk = 0; blk < 2; blk++) {
                #pragma unroll
                for (int e = 0; e < 2; e++) {
                    int n8 = 2 * kp + e;
                    int midx = t * 32 + 4 * n8 + tc;
                    int2 ma = mp[blk][0][midx];
                    int2 mbv = mp[blk][1][midx];
                    float p0 = ma.x ? ex2f(fmaf(s[blk][n8][0], SCLOG2, SHLOG2)) : 0.0f;
                    float p1 = ma.y ? ex2f(fmaf(s[blk][n8][1], SCLOG2, SHLOG2)) : 0.0f;
                    float p2 = mbv.x ? ex2f(fmaf(s[blk][n8][2], SCLOG2, SHLOG2)) : 0.0f;
                    float p3 = mbv.y ? ex2f(fmaf(s[blk][n8][3], SCLOG2, SHLOG2)) : 0.0f;
                    lsum[blk][0] += p0 + p1;
                    lsum[blk][1] += p2 + p3;
                    ah[blk][2 * e]     = h2_u32(__floats2half2_rn(p0, p1));
                    ah[blk][2 * e + 1] = h2_u32(__floats2half2_rn(p2, p3));
                }
            }
            #pragma unroll
            for (int dp = 0; dp < 4; dp++) {
                int row = (kp << 4) + (L & 7) + (((L >> 3) & 1) << 3);
                int ch  = 2 * dp + (L >> 4);
                uint32_t vhf[4];
                ldsm4t(vhf, swa(kb + 8192, row, ch));
                #pragma unroll
                for (int blk = 0; blk < 2; blk++) {
                    mma16816h(o[blk][2 * dp],     ah[blk], vhf[0], vhf[1]);
                    mma16816h(o[blk][2 * dp + 1], ah[blk], vhf[2], vhf[3]);
                }
            }
        }

        CP_WAIT(0);
        __syncthreads();
        if (t + 2 < KT64) {
            size_t off = (size_t)(t + 2) * 8192;
            copy_tile64(sb + SM_BUF + (t & 1) * SM_BUFSZ, kh_g + off, vh_g + off, tid);
            CP_COMMIT();
        }
    }

    // ---- reduce l; stage O (fp16, swizzled chunk position) into smem ----
    __syncthreads();    // mainloop smem dead; reuse from offset 0
    #pragma unroll
    for (int blk = 0; blk < 2; blk++) {
        float l0 = lsum[blk][0], l1 = lsum[blk][1];
        l0 += __shfl_xor_sync(0xffffffffu, l0, 1);
        l0 += __shfl_xor_sync(0xffffffffu, l0, 2);
        l1 += __shfl_xor_sync(0xffffffffu, l1, 1);
        l1 += __shfl_xor_sync(0xffffffffu, l1, 2);
        float inv0 = 1.0f / l0, inv1 = 1.0f / l1;

        const int rl0 = w * 32 + blk * 16 + gr;   // local row (global r&7 == rl&7)
        const int rl1 = rl0 + 8;
        const int swl = rl0 & 7;
        #pragma unroll
        for (int dn = 0; dn < 8; dn++) {
            uint32_t cperm = (uint32_t)((dn ^ swl) & 7);
            *(uint32_t*)(smem + rl0 * 144 + cperm * 16 + tc * 4) =
                h2_u32(__floats2half2_rn(o[blk][dn][0] * inv0, o[blk][dn][1] * inv0));
            *(uint32_t*)(smem + rl1 * 144 + cperm * 16 + tc * 4) =
                h2_u32(__floats2half2_rn(o[blk][dn][2] * inv1, o[blk][dn][3] * inv1));
        }
    }
    __syncthreads();

    // ---- coalesced write-out: 1024 x 16B, 8 per thread ----
    const size_t rowbase = (size_t)(b * NTOK + q0) * 512 + (size_t)h * 128;
    #pragma unroll
    for (int k2 = 0; k2 < 8; k2++) {
        int idx = tid + k2 * 128;
        int row = idx >> 3, c = idx & 7;
        uint4 v = *(const uint4*)(smem + row * 144 + c * 16);
        *(uint4*)((char*)g_Of + rowbase + (size_t)row * 512 + c * 16) = v;
    }
}

// ============================================================================
// Kernel: out-proj fp16: A = wo hi/lo (2-term), B = O single. (verified R16)
// ============================================================================
#define OSM_O  0
#define OSM_UH 65536
#define OSM_UL 98304
#define OPROJ_SMEM 131072

__global__ void __launch_bounds__(256, 1) out_mma_kernel(
    const float* __restrict__ bo, float* __restrict__ y)
{
    extern __shared__ char smem[];
    __shared__ float bias_s[64];
    const uint32_t sb = smem_u32(smem);
    const int tid = threadIdx.x;
    const int w = tid >> 5, L = tid & 31;
    const int gr = L >> 2, tc = L & 3;
    const int mw = w & 3, nw = w >> 2;

    const int n0  = blockIdx.x * 128;
    const int co0 = blockIdx.y * 64;
    const int b   = blockIdx.z;

    const char* og = (const char*)g_Of + (size_t)(b * NTOK + n0) * 512;
    const char* uh = (const char*)g_Uh + (size_t)co0 * 512;
    const char* ul = (const char*)g_Ul + (size_t)co0 * 512;
    #pragma unroll
    for (int j = 0; j < 16; j++) {
        uint32_t o = (uint32_t)(tid + j * 256) * 16;
        cp16(sb + OSM_O + o, og + o);
    }
    #pragma unroll
    for (int j = 0; j < 8; j++) {
        uint32_t o = (uint32_t)(tid + j * 256) * 16;
        cp16(sb + OSM_UH + o, uh + o);
        cp16(sb + OSM_UL + o, ul + o);
    }
    if (tid < 64) bias_s[tid] = bo[co0 + tid];
    CP_COMMIT();
    CP_WAIT(0);
    __syncthreads();

    float c[8][4];
    #pragma unroll
    for (int j = 0; j < 8; j++) { c[j][0] = c[j][1] = c[j][2] = c[j][3] = 0.0f; }

    const int arow = 16 * mw + (L & 7) + (((L >> 3) & 1) << 3);
    #pragma unroll
    for (int kq = 0; kq < 8; kq++) {
        uint32_t ah0[4], ah1[4], al0[4], al1[4];
        ldsm4(ah0, swz512(sb + OSM_UH, arow, 4 * kq + (L >> 4)));
        ldsm4(ah1, swz512(sb + OSM_UH, arow, 4 * kq + 2 + (L >> 4)));
        ldsm4(al0, swz512(sb + OSM_UL, arow, 4 * kq + (L >> 4)));
        ldsm4(al1, swz512(sb + OSM_UL, arow, 4 * kq + 2 + (L >> 4)));
        #pragma unroll
        for (int jt = 0; jt < 8; jt++) {
            uint32_t bh[4];
            int brow = 64 * nw + 8 * jt + (L & 7);
            ldsm4(bh, swz512(sb + OSM_O, brow, 4 * kq + (L >> 3)));
            mma16816h(c[jt], ah0, bh[0], bh[1]);
            mma16816h(c[jt], al0, bh[0], bh[1]);
            mma16816h(c[jt], ah1, bh[2], bh[3]);
            mma16816h(c[jt], al1, bh[2], bh[3]);
        }
    }

    const int coA = co0 + 16 * mw + gr;
    const float bA = bias_s[16 * mw + gr];
    const float bB = bias_s[16 * mw + gr + 8];
    #pragma unroll
    for (int jt = 0; jt < 8; jt++) {
        int n = n0 + 64 * nw + 8 * jt + 2 * tc;
        float2 vA; vA.x = c[jt][0] + bA; vA.y = c[jt][1] + bA;
        float2 vB; vB.x = c[jt][2] + bB; vB.y = c[jt][3] + bB;
        *(float2*)&y[(size_t)(b * CDIM + coA) * NTOK + n] = vA;
        *(float2*)&y[(size_t)(b * CDIM + coA + 8) * NTOK + n] = vB;
    }
}

// ============================================================================
// Launch
// ============================================================================
extern "C" void kernel_launch(void* const* d_in, const int* in_sizes, int n_in,
                              void* d_out, int out_size)
{
    const float* x    = (const float*)d_in[0];
    const int*   mask = (const int*)d_in[1];
    const float* wq   = (const float*)d_in[2];
    const float* bq   = (const float*)d_in[3];
    const float* wk   = (const float*)d_in[4];
    const float* bk   = (const float*)d_in[5];
    const float* wv   = (const float*)d_in[6];
    const float* bv   = (const float*)d_in[7];
    const float* wo   = (const float*)d_in[8];
    const float* bo   = (const float*)d_in[9];
    float* y = (float*)d_out;

    cudaFuncSetAttribute(attn_kernel,
                         cudaFuncAttributeMaxDynamicSharedMemorySize, ATTN_SMEM);
    cudaFuncSetAttribute(qkv_mma_kernel,
                         cudaFuncAttributeMaxDynamicSharedMemorySize, PROJ_SMEM);
    cudaFuncSetAttribute(out_mma_kernel,
                         cudaFuncAttributeMaxDynamicSharedMemorySize, OPROJ_SMEM);

    split_w_kernel<<<128, 256>>>(wq, wk, wv, wo);
    split_x_kernel<<<dim3(64, 4, 2), 256>>>(x);
    qkv_mma_kernel<<<dim3(32, 12, 2), 256, PROJ_SMEM>>>(bq, bk, bv);
    attn_kernel<<<dim3(NTOK / 128, BHDIM), 128, ATTN_SMEM>>>(mask);
    out_mma_kernel<<<dim3(32, 4, 2), 256, OPROJ_SMEM>>>(bo, y);
}